// round 2
// baseline (speedup 1.0000x reference)
#include <cuda_runtime.h>

// GatheringLoss — R2: packed f32x2 FFMA2 mainloop.
//   score = q @ keys^T ; idx = argmax_row(score) (first-max tie break)
//   kg[row] = sum_c (q-keys[idx])^2 ; vg[row] = sum_c (r-values[idx])^2
// out = [kg (65536) | vg (65536)]

#define T_TOTAL 65536
#define M_KEYS  1024
#define C_DIM   128
#define BM      128
#define BN      128
#define SA      132           // stride of A-dup tile, in float2 pairs
#define SB      132           // stride of B tile, in floats
#define THREADS 256

typedef unsigned long long ull;

__device__ __forceinline__ void ffma2(ull& d, ull a, ull b) {
    asm volatile("fma.rn.f32x2 %0, %1, %2, %0;" : "+l"(d) : "l"(a), "l"(b));
}

__global__ __launch_bounds__(THREADS, 1)
void gathering_loss_kernel(const float* __restrict__ q,
                           const float* __restrict__ r,
                           const float* __restrict__ keys,
                           const float* __restrict__ values,
                           float* __restrict__ out)
{
    extern __shared__ char smemc[];
    float2* As2 = (float2*)smemc;                          // [C_DIM][SA]: {a,a} duplicated pairs
    float*  Bs  = (float*)(smemc + C_DIM * SA * sizeof(float2)); // [C_DIM][SB]

    const int tid  = threadIdx.x;
    const int row0 = blockIdx.x * BM;
    const int tx   = tid & 15;           // key-tile coordinate (8 keys each)
    const int ty   = tid >> 4;           // row-tile coordinate (8 rows each)

    // ---- load q tile (LDG.128), transpose + duplicate into As2[k][m] = {q,q} ----
    {
        const float4* q4 = (const float4*)(q + row0 * C_DIM);
        #pragma unroll
        for (int i = 0; i < (BM * C_DIM / 4) / THREADS; ++i) {
            int idx = tid + i * THREADS;
            int m  = idx >> 5;            // row within tile (32 float4 per row)
            int k4 = (idx & 31) << 2;     // starting k
            float4 v = q4[idx];
            As2[(k4 + 0) * SA + m] = make_float2(v.x, v.x);
            As2[(k4 + 1) * SA + m] = make_float2(v.y, v.y);
            As2[(k4 + 2) * SA + m] = make_float2(v.z, v.z);
            As2[(k4 + 3) * SA + m] = make_float2(v.w, v.w);
        }
    }

    float best[8];
    int   bidx[8];
    #pragma unroll
    for (int j = 0; j < 8; ++j) { best[j] = -3.402823466e38f; bidx[j] = 0; }

    // ---- key tiles ----
    for (int t = 0; t < M_KEYS / BN; ++t) {
        __syncthreads();  // previous compute done before Bs overwrite (covers As2 fill on t==0)
        {
            const float4* k4p = (const float4*)(keys + t * BN * C_DIM);
            #pragma unroll
            for (int i = 0; i < (BN * C_DIM / 4) / THREADS; ++i) {
                int idx = tid + i * THREADS;
                int n  = idx >> 5;
                int k4 = (idx & 31) << 2;
                float4 v = k4p[idx];
                Bs[(k4 + 0) * SB + n] = v.x;
                Bs[(k4 + 1) * SB + n] = v.y;
                Bs[(k4 + 2) * SB + n] = v.z;
                Bs[(k4 + 3) * SB + n] = v.w;
            }
        }
        __syncthreads();

        ull acc[8][4];                    // acc[j][n2] = packed {score[2n2], score[2n2+1]}
        #pragma unroll
        for (int j = 0; j < 8; ++j)
            #pragma unroll
            for (int n = 0; n < 4; ++n) acc[j][n] = 0ull;  // {+0.f, +0.f}

        #pragma unroll 4
        for (int k = 0; k < C_DIM; ++k) {
            // a: 8 duplicated pairs {a,a}  (broadcast LDS.128 within warp)
            const ulonglong2* ap = (const ulonglong2*)(As2 + k * SA + ty * 8);
            ulonglong2 a01 = ap[0], a23 = ap[1], a45 = ap[2], a67 = ap[3];
            ull av[8] = {a01.x, a01.y, a23.x, a23.y, a45.x, a45.y, a67.x, a67.y};
            // b: 8 floats -> 4 adjacent pairs, free from float4 register layout
            union { float4 f; ull u[2]; } ub0, ub1;
            ub0.f = *(const float4*)(Bs + k * SB + tx * 8);
            ub1.f = *(const float4*)(Bs + k * SB + tx * 8 + 4);
            ull bv[4] = {ub0.u[0], ub0.u[1], ub1.u[0], ub1.u[1]};
            #pragma unroll
            for (int j = 0; j < 8; ++j)
                #pragma unroll
                for (int n = 0; n < 4; ++n)
                    ffma2(acc[j][n], av[j], bv[n]);
        }

        // running argmax; ascending order (n2 asc, lane .x before .y) + strict '>'
        // keeps the FIRST max, matching jnp.argmax
        #pragma unroll
        for (int j = 0; j < 8; ++j)
            #pragma unroll
            for (int n = 0; n < 4; ++n) {
                union { ull u; float2 f; } s; s.u = acc[j][n];
                int base = t * BN + tx * 8 + n * 2;
                if (s.f.x > best[j]) { best[j] = s.f.x; bidx[j] = base; }
                if (s.f.y > best[j]) { best[j] = s.f.y; bidx[j] = base + 1; }
            }
    }
    __syncthreads();  // all compute done before smem reuse

    // ---- reduce argmax across the 16 tx lanes ----
    #pragma unroll
    for (int off = 8; off >= 1; off >>= 1) {
        #pragma unroll
        for (int j = 0; j < 8; ++j) {
            float ob = __shfl_xor_sync(0xffffffffu, best[j], off);
            int   oi = __shfl_xor_sync(0xffffffffu, bidx[j], off);
            if (ob > best[j] || (ob == best[j] && oi < bidx[j])) {
                best[j] = ob;
                bidx[j] = oi;
            }
        }
    }

    int* sIdx = (int*)smemc;  // reuse As2 region
    if (tx == 0) {
        #pragma unroll
        for (int j = 0; j < 8; ++j) sIdx[ty * 8 + j] = bidx[j];
    }
    __syncthreads();

    // ---- loss epilogue: 2 threads per row, 64 elems each, shfl-combine ----
    {
        int row  = tid >> 1;
        int half = tid & 1;
        int grow = row0 + row;
        int kidx = sIdx[row];
        const float4* qp = (const float4*)(q      + grow * C_DIM + half * 64);
        const float4* kp = (const float4*)(keys   + kidx * C_DIM + half * 64);
        const float4* rp = (const float4*)(r      + grow * C_DIM + half * 64);
        const float4* vp = (const float4*)(values + kidx * C_DIM + half * 64);
        float sk = 0.f, sv = 0.f;
        #pragma unroll
        for (int c = 0; c < 16; ++c) {
            float4 a = qp[c], b = kp[c];
            float d;
            d = a.x - b.x; sk = fmaf(d, d, sk);
            d = a.y - b.y; sk = fmaf(d, d, sk);
            d = a.z - b.z; sk = fmaf(d, d, sk);
            d = a.w - b.w; sk = fmaf(d, d, sk);
            float4 e = rp[c], f = vp[c];
            d = e.x - f.x; sv = fmaf(d, d, sv);
            d = e.y - f.y; sv = fmaf(d, d, sv);
            d = e.z - f.z; sv = fmaf(d, d, sv);
            d = e.w - f.w; sv = fmaf(d, d, sv);
        }
        sk += __shfl_xor_sync(0xffffffffu, sk, 1);
        sv += __shfl_xor_sync(0xffffffffu, sv, 1);
        if (half == 0) out[grow]           = sk;
        else           out[T_TOTAL + grow] = sv;
    }
}

extern "C" void kernel_launch(void* const* d_in, const int* in_sizes, int n_in,
                              void* d_out, int out_size)
{
    const float* q      = (const float*)d_in[0];  // trend_representation (32,2048,128)
    const float* r      = (const float*)d_in[1];  // representation      (32,2048,128)
    const float* keys   = (const float*)d_in[2];  // (1024,128)
    const float* values = (const float*)d_in[3];  // (1024,128)
    float* out = (float*)d_out;

    const int smem_bytes = C_DIM * SA * (int)sizeof(float2)
                         + C_DIM * SB * (int)sizeof(float);   // 135168 + 67584 = 202752
    cudaFuncSetAttribute(gathering_loss_kernel,
                         cudaFuncAttributeMaxDynamicSharedMemorySize, smem_bytes);

    gathering_loss_kernel<<<T_TOTAL / BM, THREADS, smem_bytes>>>(q, r, keys, values, out);
}

// round 4
// speedup vs baseline: 2.2399x; 2.2399x over previous
#include <cuda_runtime.h>
#include <cuda_bf16.h>

// GatheringLoss — R4: bf16-split mma.sync (HMMA) GEMM, arch-agnostic PTX.
//   approx score = q_hi*k_hi + q_hi*k_lo + q_lo*k_hi  (fp32 accum)
//   per-row approx top-2 -> exact fp32 rescore -> argmax (first-max ties)
//   kg[row] = sum_c (q-keys[idx])^2 ; vg[row] = sum_c (r-values[idx])^2
// out = [kg (65536) | vg (65536)]

#define T_TOTAL 65536
#define M_KEYS  1024
#define C_DIM   128
#define BM      128
#define THREADS 256
#define SAB     272            // smem row stride in bytes (136 bf16) -> conflict-free ldmatrix

#define OFF_A_HI 0
#define OFF_A_LO 34816
#define OFF_B(buf) (69632 + (buf) * 69632)
#define OFF_B_LO 34816         // relative to OFF_B(buf)
#define SM_TOTAL 208896

__device__ __nv_bfloat16 g_keys_hi[M_KEYS * C_DIM];
__device__ __nv_bfloat16 g_keys_lo[M_KEYS * C_DIM];

__device__ __forceinline__ unsigned smem_u32(const void* p) {
    unsigned a;
    asm("{ .reg .u64 t; cvta.to.shared.u64 t, %1; cvt.u32.u64 %0, t; }" : "=r"(a) : "l"(p));
    return a;
}

#define LDSM_X4(r0, r1, r2, r3, a)                                             \
    asm volatile("ldmatrix.sync.aligned.m8n8.x4.shared.b16 {%0,%1,%2,%3}, [%4];" \
                 : "=r"(r0), "=r"(r1), "=r"(r2), "=r"(r3) : "r"(a))

__device__ __forceinline__ void mma_bf16(float* d, const unsigned* a,
                                         unsigned b0, unsigned b1) {
    asm volatile(
        "mma.sync.aligned.m16n8k16.row.col.f32.bf16.bf16.f32 "
        "{%0,%1,%2,%3}, {%4,%5,%6,%7}, {%8,%9}, {%0,%1,%2,%3};"
        : "+f"(d[0]), "+f"(d[1]), "+f"(d[2]), "+f"(d[3])
        : "r"(a[0]), "r"(a[1]), "r"(a[2]), "r"(a[3]), "r"(b0), "r"(b1));
}

#define CP16(dst, src) \
    asm volatile("cp.async.cg.shared.global [%0], [%1], 16;" :: "r"(dst), "l"(src))
#define CP_COMMIT() asm volatile("cp.async.commit_group;" ::: "memory")
#define CP_WAIT1()  asm volatile("cp.async.wait_group 1;"  ::: "memory")
#define CP_WAIT0()  asm volatile("cp.async.wait_group 0;"  ::: "memory")

#define UPD(s1, i1, s2, i2, v, n)                          \
    do { if ((v) > (s1)) { s2 = s1; i2 = i1; s1 = (v); i1 = (n); } \
         else if ((v) > (s2)) { s2 = (v); i2 = (n); } } while (0)

// merge sorted pair (t1,j1)>=(t2,j2) into (s1,i1,s2,i2), first-index tie-break
__device__ __forceinline__ void merge2(float& s1, int& i1, float& s2, int& i2,
                                       float t1, int j1, float t2, int j2) {
    if (t1 > s1 || (t1 == s1 && j1 < i1)) {
        float ns2; int ni2;
        if (s1 > t2 || (s1 == t2 && i1 < j2)) { ns2 = s1; ni2 = i1; }
        else                                  { ns2 = t2; ni2 = j2; }
        s1 = t1; i1 = j1; s2 = ns2; i2 = ni2;
    } else if (t1 > s2 || (t1 == s2 && j1 < i2)) {
        s2 = t1; i2 = j1;
    }
}

// ---------------- prep: split keys into bf16 hi/lo ----------------
__global__ void prep_keys_kernel(const float* __restrict__ keys) {
    int i = blockIdx.x * blockDim.x + threadIdx.x;
    if (i < M_KEYS * C_DIM) {
        float v = keys[i];
        __nv_bfloat16 h = __float2bfloat16(v);
        g_keys_hi[i] = h;
        g_keys_lo[i] = __float2bfloat16(v - __bfloat162float(h));
    }
}

// ---------------- main kernel ----------------
__global__ __launch_bounds__(THREADS, 1)
void gathering_loss_kernel(const float* __restrict__ q,
                           const float* __restrict__ r,
                           const float* __restrict__ keys,
                           const float* __restrict__ values,
                           float* __restrict__ out)
{
    extern __shared__ char smem[];
    const unsigned sb = smem_u32(smem);
    const int tid  = threadIdx.x;
    const int lane = tid & 31;
    const int wid  = tid >> 5;
    const int row0 = blockIdx.x * BM;

    // ---- A tiles: q rows -> bf16 hi/lo in smem [m][k], stride 272B ----
    {
        const float4* q4 = (const float4*)(q + (size_t)row0 * C_DIM);
        #pragma unroll
        for (int it = 0; it < (BM * C_DIM / 4) / THREADS; ++it) {
            int i = tid + it * THREADS;
            int m  = i >> 5;
            int k4 = (i & 31) << 2;
            float4 v = q4[i];
            __nv_bfloat16 hx = __float2bfloat16(v.x), hy = __float2bfloat16(v.y);
            __nv_bfloat16 hz = __float2bfloat16(v.z), hw = __float2bfloat16(v.w);
            __nv_bfloat162 h01; h01.x = hx; h01.y = hy;
            __nv_bfloat162 h23; h23.x = hz; h23.y = hw;
            __nv_bfloat162 l01, l23;
            l01.x = __float2bfloat16(v.x - __bfloat162float(hx));
            l01.y = __float2bfloat16(v.y - __bfloat162float(hy));
            l23.x = __float2bfloat16(v.z - __bfloat162float(hz));
            l23.y = __float2bfloat16(v.w - __bfloat162float(hw));
            char* p = smem + m * SAB + k4 * 2;
            *(__nv_bfloat162*)(p + OFF_A_HI)     = h01;
            *(__nv_bfloat162*)(p + OFF_A_HI + 4) = h23;
            *(__nv_bfloat162*)(p + OFF_A_LO)     = l01;
            *(__nv_bfloat162*)(p + OFF_A_LO + 4) = l23;
        }
    }

    // ---- prefetch B chunk 0 ----
    auto load_b = [&](int chunk, int buf) {
        const char* srch = (const char*)(g_keys_hi + (size_t)chunk * 128 * C_DIM);
        const char* srcl = (const char*)(g_keys_lo + (size_t)chunk * 128 * C_DIM);
        unsigned dsth = sb + OFF_B(buf);
        unsigned dstl = dsth + OFF_B_LO;
        #pragma unroll
        for (int it = 0; it < 8; ++it) {
            int s  = tid + it * THREADS;      // 2048 16B segments per half
            int n  = s >> 4;
            int ks = s & 15;
            CP16(dsth + n * SAB + ks * 16, srch + n * 256 + ks * 16);
            CP16(dstl + n * SAB + ks * 16, srcl + n * 256 + ks * 16);
        }
    };
    load_b(0, 0);
    CP_COMMIT();
    __syncthreads();   // A tiles visible to all warps

    // ---- load A fragments (held in registers for all chunks) ----
    unsigned ahi[8][4], alo[8][4];
    {
        int mat = lane >> 3;
        unsigned abase = sb + (unsigned)(wid * 16 + (lane & 7) + ((mat & 1) << 3)) * SAB
                       + ((mat >> 1) << 4);
        #pragma unroll
        for (int ks = 0; ks < 8; ++ks) {
            LDSM_X4(ahi[ks][0], ahi[ks][1], ahi[ks][2], ahi[ks][3],
                    abase + OFF_A_HI + ks * 32);
            LDSM_X4(alo[ks][0], alo[ks][1], alo[ks][2], alo[ks][3],
                    abase + OFF_A_LO + ks * 32);
        }
    }

    // B ldmatrix lane-invariant address part
    const int bmat = lane >> 3;
    const unsigned bpart = (bmat >= 2 ? OFF_B_LO : 0)
                         + (unsigned)(lane & 7) * SAB + ((bmat & 1) << 4);

    float s1a = -3.402823466e38f, s2a = -3.402823466e38f;
    float s1b = -3.402823466e38f, s2b = -3.402823466e38f;
    int i1a = 0, i2a = 0, i1b = 0, i2b = 0;

    // ---- chunk loop ----
    for (int c = 0; c < 8; ++c) {
        if (c < 7) { load_b(c + 1, (c + 1) & 1); CP_COMMIT(); CP_WAIT1(); }
        else       { CP_WAIT0(); }
        __syncthreads();   // chunk c data visible to all warps

        float acc[16][4];
        #pragma unroll
        for (int nt = 0; nt < 16; ++nt)
            #pragma unroll
            for (int j = 0; j < 4; ++j) acc[nt][j] = 0.f;

        const unsigned bbuf = sb + OFF_B(c & 1) + bpart;
        #pragma unroll
        for (int ks = 0; ks < 8; ++ks) {
            #pragma unroll
            for (int nt = 0; nt < 16; ++nt) {
                unsigned b0, b1, b2, b3;
                LDSM_X4(b0, b1, b2, b3, bbuf + (unsigned)(nt * 8) * SAB + ks * 32);
                mma_bf16(acc[nt], ahi[ks], b0, b1);   // hi*hi
                mma_bf16(acc[nt], alo[ks], b0, b1);   // lo*hi
                mma_bf16(acc[nt], ahi[ks], b2, b3);   // hi*lo
            }
        }

        // per-thread running top-2 (ascending key index, strict > = first max)
        const int colbase = c * 128 + (lane & 3) * 2;
        #pragma unroll
        for (int nt = 0; nt < 16; ++nt) {
            int nb = colbase + nt * 8;
            UPD(s1a, i1a, s2a, i2a, acc[nt][0], nb);
            UPD(s1a, i1a, s2a, i2a, acc[nt][1], nb + 1);
            UPD(s1b, i1b, s2b, i2b, acc[nt][2], nb);
            UPD(s1b, i1b, s2b, i2b, acc[nt][3], nb + 1);
        }
        __syncthreads();   // all warps done reading buf (c&1) before it is refilled
    }

    // ---- merge top-2 across the 4 lanes of each quad (same rows) ----
    #pragma unroll
    for (int off = 1; off <= 2; off <<= 1) {
        float t1 = __shfl_xor_sync(0xffffffffu, s1a, off);
        int   j1 = __shfl_xor_sync(0xffffffffu, i1a, off);
        float t2 = __shfl_xor_sync(0xffffffffu, s2a, off);
        int   j2 = __shfl_xor_sync(0xffffffffu, i2a, off);
        merge2(s1a, i1a, s2a, i2a, t1, j1, t2, j2);
        t1 = __shfl_xor_sync(0xffffffffu, s1b, off);
        j1 = __shfl_xor_sync(0xffffffffu, i1b, off);
        t2 = __shfl_xor_sync(0xffffffffu, s2b, off);
        j2 = __shfl_xor_sync(0xffffffffu, i2b, off);
        merge2(s1b, i1b, s2b, i2b, t1, j1, t2, j2);
    }

    int* idx1 = (int*)smem;          // reuse A region
    int* idx2 = idx1 + BM;
    if ((lane & 3) == 0) {
        int rw = wid * 16 + (lane >> 2);
        idx1[rw]     = i1a;  idx2[rw]     = i2a;
        idx1[rw + 8] = i1b;  idx2[rw + 8] = i2b;
    }
    __syncthreads();

    // ---- epilogue: 2 threads/row; exact fp32 rescore of 2 candidates + losses ----
    {
        int row  = tid >> 1;
        int half = tid & 1;
        int grow = row0 + row;
        int c1 = idx1[row], c2 = idx2[row];
        const float4* qp = (const float4*)(q    + (size_t)grow * C_DIM + half * 64);
        const float4* ka = (const float4*)(keys + (size_t)c1   * C_DIM + half * 64);
        const float4* kb = (const float4*)(keys + (size_t)c2   * C_DIM + half * 64);
        float sa = 0.f, sc = 0.f;
        #pragma unroll
        for (int c = 0; c < 16; ++c) {
            float4 a = qp[c], x = ka[c], y = kb[c];
            sa = fmaf(a.x, x.x, sa); sa = fmaf(a.y, x.y, sa);
            sa = fmaf(a.z, x.z, sa); sa = fmaf(a.w, x.w, sa);
            sc = fmaf(a.x, y.x, sc); sc = fmaf(a.y, y.y, sc);
            sc = fmaf(a.z, y.z, sc); sc = fmaf(a.w, y.w, sc);
        }
        sa += __shfl_xor_sync(0xffffffffu, sa, 1);
        sc += __shfl_xor_sync(0xffffffffu, sc, 1);
        int kidx = (sc > sa || (sc == sa && c2 < c1)) ? c2 : c1;

        const float4* kp = (const float4*)(keys   + (size_t)kidx * C_DIM + half * 64);
        const float4* rp = (const float4*)(r      + (size_t)grow * C_DIM + half * 64);
        const float4* vp = (const float4*)(values + (size_t)kidx * C_DIM + half * 64);
        float sk = 0.f, sv = 0.f;
        #pragma unroll
        for (int c = 0; c < 16; ++c) {
            float4 a = qp[c], b = kp[c];
            float d;
            d = a.x - b.x; sk = fmaf(d, d, sk);
            d = a.y - b.y; sk = fmaf(d, d, sk);
            d = a.z - b.z; sk = fmaf(d, d, sk);
            d = a.w - b.w; sk = fmaf(d, d, sk);
            float4 e = rp[c], f = vp[c];
            d = e.x - f.x; sv = fmaf(d, d, sv);
            d = e.y - f.y; sv = fmaf(d, d, sv);
            d = e.z - f.z; sv = fmaf(d, d, sv);
            d = e.w - f.w; sv = fmaf(d, d, sv);
        }
        sk += __shfl_xor_sync(0xffffffffu, sk, 1);
        sv += __shfl_xor_sync(0xffffffffu, sv, 1);
        if (half == 0) out[grow]           = sk;
        else           out[T_TOTAL + grow] = sv;
    }
}

extern "C" void kernel_launch(void* const* d_in, const int* in_sizes, int n_in,
                              void* d_out, int out_size)
{
    const float* q      = (const float*)d_in[0];  // trend_representation (32,2048,128)
    const float* r      = (const float*)d_in[1];  // representation      (32,2048,128)
    const float* keys   = (const float*)d_in[2];  // (1024,128)
    const float* values = (const float*)d_in[3];  // (1024,128)
    float* out = (float*)d_out;

    prep_keys_kernel<<<(M_KEYS * C_DIM + 255) / 256, 256>>>(keys);

    cudaFuncSetAttribute(gathering_loss_kernel,
                         cudaFuncAttributeMaxDynamicSharedMemorySize, SM_TOTAL);
    gathering_loss_kernel<<<T_TOTAL / BM, THREADS, SM_TOTAL>>>(q, r, keys, values, out);
}

// round 5
// speedup vs baseline: 2.2529x; 1.0058x over previous
#include <cuda_runtime.h>
#include <cuda_bf16.h>

// GatheringLoss — R5: R4 + register-pressure fix (acc split into nt-halves).
//   approx score = q_hi*k_hi + q_hi*k_lo + q_lo*k_hi  (fp32 accum, HMMA)
//   per-row approx top-2 -> exact fp32 rescore -> argmax (first-max ties)
// out = [kg (65536) | vg (65536)]

#define T_TOTAL 65536
#define M_KEYS  1024
#define C_DIM   128
#define BM      128
#define THREADS 256
#define SAB     272            // smem row stride in bytes -> conflict-free ldmatrix

#define OFF_A_HI 0
#define OFF_A_LO 34816
#define OFF_B(buf) (69632 + (buf) * 69632)
#define OFF_B_LO 34816         // relative to OFF_B(buf)
#define SM_TOTAL 208896

__device__ __nv_bfloat16 g_keys_hi[M_KEYS * C_DIM];
__device__ __nv_bfloat16 g_keys_lo[M_KEYS * C_DIM];

__device__ __forceinline__ unsigned smem_u32(const void* p) {
    unsigned a;
    asm("{ .reg .u64 t; cvta.to.shared.u64 t, %1; cvt.u32.u64 %0, t; }" : "=r"(a) : "l"(p));
    return a;
}

#define LDSM_X4(r0, r1, r2, r3, a)                                             \
    asm volatile("ldmatrix.sync.aligned.m8n8.x4.shared.b16 {%0,%1,%2,%3}, [%4];" \
                 : "=r"(r0), "=r"(r1), "=r"(r2), "=r"(r3) : "r"(a))

__device__ __forceinline__ void mma_bf16(float* d, const unsigned* a,
                                         unsigned b0, unsigned b1) {
    asm volatile(
        "mma.sync.aligned.m16n8k16.row.col.f32.bf16.bf16.f32 "
        "{%0,%1,%2,%3}, {%4,%5,%6,%7}, {%8,%9}, {%0,%1,%2,%3};"
        : "+f"(d[0]), "+f"(d[1]), "+f"(d[2]), "+f"(d[3])
        : "r"(a[0]), "r"(a[1]), "r"(a[2]), "r"(a[3]), "r"(b0), "r"(b1));
}

#define CP16(dst, src) \
    asm volatile("cp.async.cg.shared.global [%0], [%1], 16;" :: "r"(dst), "l"(src))
#define CP_COMMIT() asm volatile("cp.async.commit_group;" ::: "memory")
#define CP_WAIT1()  asm volatile("cp.async.wait_group 1;"  ::: "memory")
#define CP_WAIT0()  asm volatile("cp.async.wait_group 0;"  ::: "memory")

#define UPD(s1, i1, s2, i2, v, n)                          \
    do { if ((v) > (s1)) { s2 = s1; i2 = i1; s1 = (v); i1 = (n); } \
         else if ((v) > (s2)) { s2 = (v); i2 = (n); } } while (0)

__device__ __forceinline__ void merge2(float& s1, int& i1, float& s2, int& i2,
                                       float t1, int j1, float t2, int j2) {
    if (t1 > s1 || (t1 == s1 && j1 < i1)) {
        float ns2; int ni2;
        if (s1 > t2 || (s1 == t2 && i1 < j2)) { ns2 = s1; ni2 = i1; }
        else                                  { ns2 = t2; ni2 = j2; }
        s1 = t1; i1 = j1; s2 = ns2; i2 = ni2;
    } else if (t1 > s2 || (t1 == s2 && j1 < i2)) {
        s2 = t1; i2 = j1;
    }
}

// ---------------- prep: split keys into bf16 hi/lo ----------------
__global__ void prep_keys_kernel(const float* __restrict__ keys) {
    int i = blockIdx.x * blockDim.x + threadIdx.x;
    if (i < M_KEYS * C_DIM) {
        float v = keys[i];
        __nv_bfloat16 h = __float2bfloat16(v);
        g_keys_hi[i] = h;
        g_keys_lo[i] = __float2bfloat16(v - __bfloat162float(h));
    }
}

// ---------------- main kernel ----------------
__global__ __launch_bounds__(THREADS, 1)
void gathering_loss_kernel(const float* __restrict__ q,
                           const float* __restrict__ r,
                           const float* __restrict__ keys,
                           const float* __restrict__ values,
                           float* __restrict__ out)
{
    extern __shared__ char smem[];
    const unsigned sb = smem_u32(smem);
    const int tid  = threadIdx.x;
    const int lane = tid & 31;
    const int wid  = tid >> 5;
    const int row0 = blockIdx.x * BM;

    // ---- A tiles: q rows -> bf16 hi/lo in smem [m][k], stride 272B ----
    {
        const float4* q4 = (const float4*)(q + (size_t)row0 * C_DIM);
        #pragma unroll
        for (int it = 0; it < (BM * C_DIM / 4) / THREADS; ++it) {
            int i = tid + it * THREADS;
            int m  = i >> 5;
            int k4 = (i & 31) << 2;
            float4 v = q4[i];
            __nv_bfloat16 hx = __float2bfloat16(v.x), hy = __float2bfloat16(v.y);
            __nv_bfloat16 hz = __float2bfloat16(v.z), hw = __float2bfloat16(v.w);
            __nv_bfloat162 h01; h01.x = hx; h01.y = hy;
            __nv_bfloat162 h23; h23.x = hz; h23.y = hw;
            __nv_bfloat162 l01, l23;
            l01.x = __float2bfloat16(v.x - __bfloat162float(hx));
            l01.y = __float2bfloat16(v.y - __bfloat162float(hy));
            l23.x = __float2bfloat16(v.z - __bfloat162float(hz));
            l23.y = __float2bfloat16(v.w - __bfloat162float(hw));
            char* p = smem + m * SAB + k4 * 2;
            *(__nv_bfloat162*)(p + OFF_A_HI)     = h01;
            *(__nv_bfloat162*)(p + OFF_A_HI + 4) = h23;
            *(__nv_bfloat162*)(p + OFF_A_LO)     = l01;
            *(__nv_bfloat162*)(p + OFF_A_LO + 4) = l23;
        }
    }

    // ---- B chunk loader (cp.async, double buffered) ----
    auto load_b = [&](int chunk, int buf) {
        const char* srch = (const char*)(g_keys_hi + (size_t)chunk * 128 * C_DIM);
        const char* srcl = (const char*)(g_keys_lo + (size_t)chunk * 128 * C_DIM);
        unsigned dsth = sb + OFF_B(buf);
        unsigned dstl = dsth + OFF_B_LO;
        #pragma unroll
        for (int it = 0; it < 8; ++it) {
            int s  = tid + it * THREADS;
            int n  = s >> 4;
            int ks = s & 15;
            CP16(dsth + n * SAB + ks * 16, srch + n * 256 + ks * 16);
            CP16(dstl + n * SAB + ks * 16, srcl + n * 256 + ks * 16);
        }
    };
    load_b(0, 0);
    CP_COMMIT();
    __syncthreads();

    // ---- A fragments: persistent in registers (64 regs) ----
    unsigned ahi[8][4], alo[8][4];
    {
        int mat = lane >> 3;
        unsigned abase = sb + (unsigned)(wid * 16 + (lane & 7) + ((mat & 1) << 3)) * SAB
                       + ((mat >> 1) << 4);
        #pragma unroll
        for (int ks = 0; ks < 8; ++ks) {
            LDSM_X4(ahi[ks][0], ahi[ks][1], ahi[ks][2], ahi[ks][3],
                    abase + OFF_A_HI + ks * 32);
            LDSM_X4(alo[ks][0], alo[ks][1], alo[ks][2], alo[ks][3],
                    abase + OFF_A_LO + ks * 32);
        }
    }

    const int bmat = lane >> 3;
    const unsigned bpart = (bmat >= 2 ? OFF_B_LO : 0)
                         + (unsigned)(lane & 7) * SAB + ((bmat & 1) << 4);

    float s1a = -3.402823466e38f, s2a = -3.402823466e38f;
    float s1b = -3.402823466e38f, s2b = -3.402823466e38f;
    int i1a = 0, i2a = 0, i1b = 0, i2b = 0;

    // ---- chunk loop (kept rolled: I$ friendly) ----
    #pragma unroll 1
    for (int c = 0; c < 8; ++c) {
        if (c < 7) { load_b(c + 1, (c + 1) & 1); CP_COMMIT(); CP_WAIT1(); }
        else       { CP_WAIT0(); }
        __syncthreads();

        const unsigned bbuf = sb + OFF_B(c & 1) + bpart;

        // two nt-halves of 8 -> acc is only 32 regs live, 8 independent chains
        #pragma unroll
        for (int h = 0; h < 2; ++h) {
            float acc[8][4];
            #pragma unroll
            for (int j = 0; j < 8; ++j)
                #pragma unroll
                for (int x = 0; x < 4; ++x) acc[j][x] = 0.f;

            #pragma unroll
            for (int ks = 0; ks < 8; ++ks) {
                #pragma unroll
                for (int j = 0; j < 8; ++j) {
                    const int nt = h * 8 + j;
                    unsigned b0, b1, b2, b3;
                    LDSM_X4(b0, b1, b2, b3, bbuf + (unsigned)(nt * 8) * SAB + ks * 32);
                    mma_bf16(acc[j], ahi[ks], b0, b1);   // hi*hi
                    mma_bf16(acc[j], alo[ks], b0, b1);   // lo*hi
                    mma_bf16(acc[j], ahi[ks], b2, b3);   // hi*lo
                }
            }

            const int colbase = c * 128 + h * 64 + (lane & 3) * 2;
            #pragma unroll
            for (int j = 0; j < 8; ++j) {
                int nb = colbase + j * 8;
                UPD(s1a, i1a, s2a, i2a, acc[j][0], nb);
                UPD(s1a, i1a, s2a, i2a, acc[j][1], nb + 1);
                UPD(s1b, i1b, s2b, i2b, acc[j][2], nb);
                UPD(s1b, i1b, s2b, i2b, acc[j][3], nb + 1);
            }
        }
        __syncthreads();
    }

    // ---- merge top-2 across the 4 lanes of each quad ----
    #pragma unroll
    for (int off = 1; off <= 2; off <<= 1) {
        float t1 = __shfl_xor_sync(0xffffffffu, s1a, off);
        int   j1 = __shfl_xor_sync(0xffffffffu, i1a, off);
        float t2 = __shfl_xor_sync(0xffffffffu, s2a, off);
        int   j2 = __shfl_xor_sync(0xffffffffu, i2a, off);
        merge2(s1a, i1a, s2a, i2a, t1, j1, t2, j2);
        t1 = __shfl_xor_sync(0xffffffffu, s1b, off);
        j1 = __shfl_xor_sync(0xffffffffu, i1b, off);
        t2 = __shfl_xor_sync(0xffffffffu, s2b, off);
        j2 = __shfl_xor_sync(0xffffffffu, i2b, off);
        merge2(s1b, i1b, s2b, i2b, t1, j1, t2, j2);
    }

    int* idx1 = (int*)smem;          // reuse A region
    int* idx2 = idx1 + BM;
    if ((lane & 3) == 0) {
        int rw = wid * 16 + (lane >> 2);
        idx1[rw]     = i1a;  idx2[rw]     = i2a;
        idx1[rw + 8] = i1b;  idx2[rw + 8] = i2b;
    }
    __syncthreads();

    // ---- epilogue: 2 threads/row; exact fp32 rescore + losses ----
    {
        int row  = tid >> 1;
        int half = tid & 1;
        int grow = row0 + row;
        int c1 = idx1[row], c2 = idx2[row];
        const float4* qp = (const float4*)(q    + (size_t)grow * C_DIM + half * 64);
        const float4* ka = (const float4*)(keys + (size_t)c1   * C_DIM + half * 64);
        const float4* kb = (const float4*)(keys + (size_t)c2   * C_DIM + half * 64);
        float sa = 0.f, sc = 0.f;
        #pragma unroll
        for (int c = 0; c < 16; ++c) {
            float4 a = qp[c], x = ka[c], y = kb[c];
            sa = fmaf(a.x, x.x, sa); sa = fmaf(a.y, x.y, sa);
            sa = fmaf(a.z, x.z, sa); sa = fmaf(a.w, x.w, sa);
            sc = fmaf(a.x, y.x, sc); sc = fmaf(a.y, y.y, sc);
            sc = fmaf(a.z, y.z, sc); sc = fmaf(a.w, y.w, sc);
        }
        sa += __shfl_xor_sync(0xffffffffu, sa, 1);
        sc += __shfl_xor_sync(0xffffffffu, sc, 1);
        int kidx = (sc > sa || (sc == sa && c2 < c1)) ? c2 : c1;

        const float4* kp = (const float4*)(keys   + (size_t)kidx * C_DIM + half * 64);
        const float4* rp = (const float4*)(r      + (size_t)grow * C_DIM + half * 64);
        const float4* vp = (const float4*)(values + (size_t)kidx * C_DIM + half * 64);
        float sk = 0.f, sv = 0.f;
        #pragma unroll
        for (int c = 0; c < 16; ++c) {
            float4 a = qp[c], b = kp[c];
            float d;
            d = a.x - b.x; sk = fmaf(d, d, sk);
            d = a.y - b.y; sk = fmaf(d, d, sk);
            d = a.z - b.z; sk = fmaf(d, d, sk);
            d = a.w - b.w; sk = fmaf(d, d, sk);
            float4 e = rp[c], f = vp[c];
            d = e.x - f.x; sv = fmaf(d, d, sv);
            d = e.y - f.y; sv = fmaf(d, d, sv);
            d = e.z - f.z; sv = fmaf(d, d, sv);
            d = e.w - f.w; sv = fmaf(d, d, sv);
        }
        sk += __shfl_xor_sync(0xffffffffu, sk, 1);
        sv += __shfl_xor_sync(0xffffffffu, sv, 1);
        if (half == 0) out[grow]           = sk;
        else           out[T_TOTAL + grow] = sv;
    }
}

extern "C" void kernel_launch(void* const* d_in, const int* in_sizes, int n_in,
                              void* d_out, int out_size)
{
    const float* q      = (const float*)d_in[0];
    const float* r      = (const float*)d_in[1];
    const float* keys   = (const float*)d_in[2];
    const float* values = (const float*)d_in[3];
    float* out = (float*)d_out;

    prep_keys_kernel<<<(M_KEYS * C_DIM + 255) / 256, 256>>>(keys);

    cudaFuncSetAttribute(gathering_loss_kernel,
                         cudaFuncAttributeMaxDynamicSharedMemorySize, SM_TOTAL);
    gathering_loss_kernel<<<T_TOTAL / BM, THREADS, SM_TOTAL>>>(q, r, keys, values, out);
}